// round 3
// baseline (speedup 1.0000x reference)
#include <cuda_runtime.h>

#define WW 4096
#define HH 4096
#define ROWS 64            // output rows per warp
#define OUTW 124           // output columns per strip (warp loads 128, aligned)
#define NSTRIPS 34         // ceil coverage of 4096 columns
#define WARPS 8
#define GRIDY 8            // 4096 / (ROWS * WARPS)
#define NBLOCKS (NSTRIPS * GRIDY)
#define NTHREADS 256

// Accumulators: zeroed at load; the last block resets them each replay.
__device__ double g_sum_d2 = 0.0;
__device__ double g_sum_G  = 0.0;
__device__ double g_cnt    = 0.0;
__device__ unsigned int g_done = 0u;

__device__ __forceinline__ int reflc(int i) {          // reflect-101, width WW
    if (i < 0) i = -i;
    if (i >= WW) i = 2 * WW - 2 - i;
    return i;
}

struct DT { float4 d, t; };

__device__ __forceinline__ DT load_dt(const float* __restrict__ pred,
                                      const float* __restrict__ target,
                                      int rowoff, int xb, bool inx) {
    DT r;
    if (inx) {
        float4 p = __ldg((const float4*)(pred + rowoff + xb));
        float4 t = __ldg((const float4*)(target + rowoff + xb));
        r.t = t;
        r.d = make_float4(p.x - t.x, p.y - t.y, p.z - t.z, p.w - t.w);
    } else {
        int c0 = reflc(xb), c1 = reflc(xb + 1), c2 = reflc(xb + 2), c3 = reflc(xb + 3);
        float t0 = __ldg(target + rowoff + c0), p0 = __ldg(pred + rowoff + c0);
        float t1 = __ldg(target + rowoff + c1), p1 = __ldg(pred + rowoff + c1);
        float t2 = __ldg(target + rowoff + c2), p2 = __ldg(pred + rowoff + c2);
        float t3 = __ldg(target + rowoff + c3), p3 = __ldg(pred + rowoff + c3);
        r.t = make_float4(t0, t1, t2, t3);
        r.d = make_float4(p0 - t0, p1 - t1, p2 - t2, p3 - t3);
    }
    return r;
}

// Horizontal combined taps on 4 columns: A = [1,4,6,4,1], B = [-1,-2,0,2,1]
// Halo (2 cols each side) via 4 shuffles per warp per row.
__device__ __forceinline__ void hpass4(float4 d, float4& A, float4& B) {
    float wm2 = __shfl_up_sync(0xffffffffu,   d.z, 1);
    float wm1 = __shfl_up_sync(0xffffffffu,   d.w, 1);
    float wp4 = __shfl_down_sync(0xffffffffu, d.x, 1);
    float wp5 = __shfl_down_sync(0xffffffffu, d.y, 1);
    float w0 = d.x, w1 = d.y, w2 = d.z, w3 = d.w;
    A.x = fmaf(6.f, w0, fmaf(4.f, wm1 + w1, wm2 + w2));
    B.x = fmaf(2.f, w1 - wm1, w2 - wm2);
    A.y = fmaf(6.f, w1, fmaf(4.f, w0 + w2, wm1 + w3));
    B.y = fmaf(2.f, w2 - w0, w3 - wm1);
    A.z = fmaf(6.f, w2, fmaf(4.f, w1 + w3, w0 + wp4));
    B.z = fmaf(2.f, w3 - w1, wp4 - w0);
    A.w = fmaf(6.f, w3, fmaf(4.f, w2 + wp4, w1 + wp5));
    B.w = fmaf(2.f, wp4 - w2, wp5 - w1);
}

__device__ __forceinline__ void mse4(float4 d, float4 t, float4 mo,
                                     float4& accD2, float4& accC) {
    float m;
    m = (t.x > 0.f) ? mo.x : 0.f; accD2.x = fmaf(m * d.x, d.x, accD2.x); accC.x += m;
    m = (t.y > 0.f) ? mo.y : 0.f; accD2.y = fmaf(m * d.y, d.y, accD2.y); accC.y += m;
    m = (t.z > 0.f) ? mo.z : 0.f; accD2.z = fmaf(m * d.z, d.z, accD2.z); accC.z += m;
    m = (t.w > 0.f) ? mo.w : 0.f; accD2.w = fmaf(m * d.w, d.w, accD2.w); accC.w += m;
}

__device__ __forceinline__ float vcomp(float b0, float b1, float b2, float b3, float b4,
                                       float a0, float a1, float a3, float a4, float mo) {
    float dx = fmaf(6.f, b2, fmaf(4.f, b1 + b3, b0 + b4));
    float dy = fmaf(2.f, a3 - a1, a4 - a0);
    float g  = fmaf(-dy, dy, dx * dx);
    return mo * g;
}

__device__ __forceinline__ void vpass4(const float4& A0, const float4& A1,
                                       const float4& A3, const float4& A4,
                                       const float4& B0, const float4& B1,
                                       const float4& B2, const float4& B3,
                                       const float4& B4, float4 mo, float4& accG) {
    accG.x += vcomp(B0.x, B1.x, B2.x, B3.x, B4.x, A0.x, A1.x, A3.x, A4.x, mo.x);
    accG.y += vcomp(B0.y, B1.y, B2.y, B3.y, B4.y, A0.y, A1.y, A3.y, A4.y, mo.y);
    accG.z += vcomp(B0.z, B1.z, B2.z, B3.z, B4.z, A0.z, A1.z, A3.z, A4.z, mo.z);
    accG.w += vcomp(B0.w, B1.w, B2.w, B3.w, B4.w, A0.w, A1.w, A3.w, A4.w, mo.w);
}

__global__ __launch_bounds__(NTHREADS)
void loss_kernel(const float* __restrict__ pred, const float* __restrict__ target,
                 float* __restrict__ out) {
    __shared__ float s_d2[WARPS], s_g[WARPS], s_c[WARPS];
    __shared__ bool  s_last;

    const int lane = threadIdx.x & 31;
    const int wid  = threadIdx.x >> 5;
    const int s    = blockIdx.x;                     // column strip
    const int y0   = (blockIdx.y * WARPS + wid) * ROWS;

    const int xb   = s * OUTW - 4 + lane * 4;        // 16B-aligned when interior
    const bool inx = (xb >= 0) && (xb + 3 < WW);

    // per-component output mask (strip output window ∩ image)
    const int outlo = s * OUTW - 2;
    const int outhi = s * OUTW + 121;
    float4 mo;
    mo.x = (xb     >= outlo && xb     <= outhi && (unsigned)xb       < WW) ? 1.f : 0.f;
    mo.y = (xb + 1 >= outlo && xb + 1 <= outhi && (unsigned)(xb + 1) < WW) ? 1.f : 0.f;
    mo.z = (xb + 2 >= outlo && xb + 2 <= outhi && (unsigned)(xb + 2) < WW) ? 1.f : 0.f;
    mo.w = (xb + 3 >= outlo && xb + 3 <= outhi && (unsigned)(xb + 3) < WW) ? 1.f : 0.f;

    float4 accD2 = make_float4(0, 0, 0, 0);
    float4 accG  = make_float4(0, 0, 0, 0);
    float4 accC  = make_float4(0, 0, 0, 0);

    float4 A0, A1, A2, A3, B0, B1, B2, B3;

    // ---- Prologue: rows y0-2 .. y0+1 (row reflect only at top band) ----
    {
        int r, rr;
        r = y0 - 2; rr = (r < 0) ? -r : r;
        { DT q = load_dt(pred, target, rr * WW, xb, inx); hpass4(q.d, A0, B0); }
        r = y0 - 1; rr = (r < 0) ? -r : r;
        { DT q = load_dt(pred, target, rr * WW, xb, inx); hpass4(q.d, A1, B1); }
        { DT q = load_dt(pred, target, y0 * WW, xb, inx);
          mse4(q.d, q.t, mo, accD2, accC); hpass4(q.d, A2, B2); }
        { DT q = load_dt(pred, target, (y0 + 1) * WW, xb, inx);
          mse4(q.d, q.t, mo, accD2, accC); hpass4(q.d, A3, B3); }
    }

    // ---- Main: input rows y0+2 .. y0+ROWS-1 (always interior rows) ----
    int rowoff = (y0 + 2) * WW;
    #pragma unroll 5
    for (int i = 0; i < ROWS - 2; i++) {
        DT q = load_dt(pred, target, rowoff, xb, inx);
        rowoff += WW;
        mse4(q.d, q.t, mo, accD2, accC);
        float4 A4, B4; hpass4(q.d, A4, B4);
        vpass4(A0, A1, A3, A4, B0, B1, B2, B3, B4, mo, accG);
        A0 = A1; A1 = A2; A2 = A3; A3 = A4;
        B0 = B1; B1 = B2; B2 = B3; B3 = B4;
    }

    // ---- Epilogue: rows y0+ROWS, y0+ROWS+1 (bottom reflect; no MSE) ----
    #pragma unroll
    for (int k = 0; k < 2; k++) {
        int r = y0 + ROWS + k;
        int rr = (r >= HH) ? (2 * HH - 2 - r) : r;
        DT q = load_dt(pred, target, rr * WW, xb, inx);
        float4 A4, B4; hpass4(q.d, A4, B4);
        vpass4(A0, A1, A3, A4, B0, B1, B2, B3, B4, mo, accG);
        A0 = A1; A1 = A2; A2 = A3; A3 = A4;
        B0 = B1; B1 = B2; B2 = B3; B3 = B4;
    }

    // ---- Reduce: fold float4 -> scalar, warp shuffle, smem, atomics ----
    float rd2 = (accD2.x + accD2.y) + (accD2.z + accD2.w);
    float rg  = (accG.x  + accG.y ) + (accG.z  + accG.w );
    float rc  = (accC.x  + accC.y ) + (accC.z  + accC.w );
    #pragma unroll
    for (int off = 16; off > 0; off >>= 1) {
        rd2 += __shfl_down_sync(0xffffffffu, rd2, off);
        rg  += __shfl_down_sync(0xffffffffu, rg,  off);
        rc  += __shfl_down_sync(0xffffffffu, rc,  off);
    }
    if (lane == 0) { s_d2[wid] = rd2; s_g[wid] = rg; s_c[wid] = rc; }
    __syncthreads();
    if (threadIdx.x == 0) {
        float t2 = 0.f, tg = 0.f, tc = 0.f;
        #pragma unroll
        for (int i = 0; i < WARPS; i++) { t2 += s_d2[i]; tg += s_g[i]; tc += s_c[i]; }
        atomicAdd(&g_sum_d2, (double)t2);
        atomicAdd(&g_sum_G,  (double)tg);
        atomicAdd(&g_cnt,    (double)tc);
        __threadfence();
        unsigned int done = atomicAdd(&g_done, 1u);
        s_last = (done == NBLOCKS - 1);
    }
    __syncthreads();

    // ---- Last block finalizes and resets (single launch per replay) ----
    if (s_last && threadIdx.x == 0) {
        double sd2 = *(volatile double*)&g_sum_d2;
        double sg  = *(volatile double*)&g_sum_G;
        double n   = *(volatile double*)&g_cnt;
        if (n < 1.0) n = 1.0;
        double mae = sd2 / n;
        // taps were 16x true dx/dy -> scale by 1/256
        double G = sg / (256.0 * (double)WW * (double)HH);
        out[0] = (float)(0.2 * G + 0.8 * mae);
        *(volatile double*)&g_sum_d2 = 0.0;
        *(volatile double*)&g_sum_G  = 0.0;
        *(volatile double*)&g_cnt    = 0.0;
        *(volatile unsigned int*)&g_done = 0u;
    }
}

extern "C" void kernel_launch(void* const* d_in, const int* in_sizes, int n_in,
                              void* d_out, int out_size) {
    const float* pred   = (const float*)d_in[0];
    const float* target = (const float*)d_in[1];
    float* out = (float*)d_out;

    dim3 grid(NSTRIPS, GRIDY);
    loss_kernel<<<grid, NTHREADS>>>(pred, target, out);
}